// round 12
// baseline (speedup 1.0000x reference)
#include <cuda_runtime.h>
#include <cuda_fp16.h>
#include <cstdint>

#define BB 16
#define CC 256
#define HH 64
#define WW 64
#define SSD 512
#define HW 4096

// A chunk image (fp16 pairs): [128 oc rows][20 u32 words]; word j = ci pair (2j,2j+1), j<16; 4 pad
#define A_CHUNK_U32   2560
#define A_CHUNK_BYTES 10240
#define N_ABUF 6
#define WF_STAGE (9*2*8*A_CHUNK_U32)

// B buffer (fp16 pairs): [16 k2 words][6 rows][68 slots]; slot = col+2 (0,1,66,67 zero)
#define B_K2STR 408            // 6*68 ; 408 mod 32 = 24 -> conflict-free b-frags
#define B_ROWSTR 68
#define B_BUF_U32 (16*B_K2STR) // 6528

// smem u32 map: [0..96B) 12 mbars, styles at u32 24
#define SM_STY 24
#define SM_A0  288
#define SM_B0  (288 + N_ABUF*A_CHUNK_U32)   // 15648
#define SM_U32 (SM_B0 + 2*B_BUF_U32)        // 28704
#define SM_BYTES (SM_U32*4)                 // 114816

__device__ float    g_inter[BB*CC*HW];
__device__ float    g_style[2*BB*CC];
__device__ float    g_demod[2*BB*CC];
__device__ float    g_Rt[2*CC*CC];
__device__ uint32_t g_Wf[2*WF_STAGE];

// ---------------- helpers ----------------
__device__ __forceinline__ uint32_t smem_u32(const void* p) {
    uint32_t a;
    asm("{ .reg .u64 t; cvta.to.shared.u64 t, %1; cvt.u32.u64 %0, t; }" : "=r"(a) : "l"(p));
    return a;
}
__device__ __forceinline__ uint32_t packh2(float lo, float hi) {
    __half2 h = __floats2half2_rn(lo, hi);
    return *(uint32_t*)&h;
}
__device__ __forceinline__ void mbar_wait(uint32_t mbar, uint32_t parity) {
    asm volatile(
        "{\n\t.reg .pred P;\n\t"
        "WL_%=:\n\t"
        "mbarrier.try_wait.parity.acquire.cta.shared::cta.b64 P, [%0], %1, 0x989680;\n\t"
        "@P bra.uni WD_%=;\n\t"
        "bra.uni WL_%=;\n\t"
        "WD_%=:\n\t}"
        :: "r"(mbar), "r"(parity) : "memory");
}
#define MBAR_INIT(a,n)  asm volatile("mbarrier.init.shared.b64 [%0], %1;" :: "r"(a), "r"((uint32_t)(n)) : "memory")
#define MBAR_ARRIVE(a)  asm volatile("mbarrier.arrive.release.cta.shared::cta.b64 _, [%0];" :: "r"(a) : "memory")

#define MMA_F16(d, a0,a1,a2,a3, b0,b1) \
    asm volatile("mma.sync.aligned.m16n8k16.row.col.f32.f16.f16.f32 " \
        "{%0,%1,%2,%3}, {%4,%5,%6,%7}, {%8,%9}, {%0,%1,%2,%3};" \
        : "+f"((d)[0]), "+f"((d)[1]), "+f"((d)[2]), "+f"((d)[3]) \
        : "r"(a0), "r"(a1), "r"(a2), "r"(a3), "r"(b0), "r"(b1))

// ---------------- fused prep (style + Rt + Wf) via flat grid ----------------
// blocks 0..127: style (st,b,chgrp) ; 128..639: Rt (st,ci) ; 640..927: Wf
__global__ void k_prep(const float* __restrict__ w1v, const float* __restrict__ s1w,
                       const float* __restrict__ s1b, const float* __restrict__ c1w,
                       const float* __restrict__ w2v, const float* __restrict__ s2w,
                       const float* __restrict__ s2b, const float* __restrict__ c2w) {
    __shared__ float s[SSD];
    const int bid = blockIdx.x, t = threadIdx.x;

    if (bid < 128) {
        const int st = bid >> 6, rem = bid & 63;
        const int b = rem & 15, chgrp = rem >> 4;
        const float* wv = st ? w2v : w1v;
        const float* sw = st ? s2w : s1w;
        const float* sb = st ? s2b : s1b;
        s[t] = wv[b*SSD + t]; s[t+256] = wv[b*SSD + 256 + t];
        __syncthreads();
        const int ch   = chgrp*64 + (t >> 2);
        const int part = t & 3;
        float acc = 0.f;
        const float* rw = sw + (size_t)ch*SSD + part*128;
        const float* sp = s + part*128;
        #pragma unroll 8
        for (int j = 0; j < 128; j++) acc += sp[j] * rw[j];
        acc += __shfl_xor_sync(0xFFFFFFFF, acc, 1);
        acc += __shfl_xor_sync(0xFFFFFFFF, acc, 2);
        if (part == 0) g_style[st*BB*CC + b*CC + ch] = acc * 0.03125f + sb[ch];
    } else if (bid < 640) {
        const int idx = bid - 128;
        const int st = idx >> 8, ci = idx & 255;
        const float* w = st ? c2w : c1w;
        const float* src = w + (t*CC + ci)*9;
        float s2 = 0.f;
        #pragma unroll
        for (int k = 0; k < 9; k++) { float v = src[k]; s2 += v*v; }
        g_Rt[st*CC*CC + ci*CC + t] = s2;
    } else {
        const int idx = bid - 640;           // 0..287
        const int k = idx % 9, r = idx / 9;  // r: 0..31
        const int oh = r & 1, cc = (r >> 1) & 7, st = r >> 4;
        const float* w = st ? c2w : c1w;
        uint32_t* dst = g_Wf + (size_t)st*WF_STAGE + (size_t)((k*2 + oh)*8 + cc)*A_CHUNK_U32;
        for (int f = t; f < A_CHUNK_U32; f += 256) {
            const int row = f / 20;
            const int j   = f - row*20;
            uint32_t v = 0;
            if (j < 16) {
                const size_t rb = (size_t)((oh*128 + row)*CC + cc*32 + 2*j)*9 + k;
                v = packh2(w[rb], w[rb + 9]);
            }
            dst[f] = v;
        }
    }
}

// coalesced demod: thread = channel, row-major Rt scan
__global__ void k_demod() {
    const int st = blockIdx.z, b = blockIdx.x, t = threadIdx.x;
    __shared__ float st2[CC];
    float s = g_style[st*BB*CC + b*CC + t];
    st2[t] = s*s;
    __syncthreads();
    const float* rt = g_Rt + st*CC*CC + t;
    float acc = 0.f;
    #pragma unroll 8
    for (int i = 0; i < CC; i++) acc += st2[i] * rt[(size_t)i*CC];
    g_demod[st*BB*CC + b*CC + t] = rsqrtf(acc + 1e-8f);
}

// ---------------- fp16 mma.sync implicit-GEMM conv ----------------
// CTA: M=128 oc x N=256 px (4 image rows). 8 warps = 2 Mwarps x 4 Nwarps,
// warp tile 64x64. K = 2304 in 72 chunks (2 x m16n8k16 per ks, 64 MMA/warp).
// A: 6-slot cp.async.bulk ring (full tx-mbars + empty 8-arrival mbars);
// B: 6 input rows per cc, double-buffered, one __syncthreads per cc.
__global__ __launch_bounds__(256, 1)
void k_conv(const float* __restrict__ xg, float* __restrict__ outg,
            const float* __restrict__ noise, const float* __restrict__ nw,
            int st) {
    extern __shared__ uint32_t smu[];
    float* smf = (float*)smu;
    const uint32_t base = smem_u32(smu);

    const float* xin  = (st == 0) ? xg : g_inter;
    float*       outp = (st == 0) ? g_inter : outg;

    const int tid = threadIdx.x, wid = tid >> 5, lane = tid & 31;
    const int woc = wid & 1;                 // M half (64 oc)
    const int wn  = wid >> 1;                // output row 0..3
    const int y0  = blockIdx.x * 4;
    const int ocsel = blockIdx.y;
    const int oc0 = ocsel * 128;
    const int b   = blockIdx.z;

    const int pcp = tid >> 4;          // ci pair 0..15
    const int ppx = (tid & 15) * 4;    // px 0..60

    // zero only the boundary slots (0,1,66,67) of both B buffers
    for (int i = tid; i < 768; i += 256) {
        const int buf = i / 384, rem = i - buf*384;
        const int line = rem >> 2, q = rem & 3;
        const int k2 = line / 6, row = line - k2*6;
        const int slot = (q < 2) ? q : (64 + q);
        smu[SM_B0 + buf*B_BUF_U32 + k2*B_K2STR + row*B_ROWSTR + slot] = 0;
    }
    smf[SM_STY + tid] = g_style[st*BB*CC + b*CC + tid];
    if (tid == 0) {
        #pragma unroll
        for (int s = 0; s < 6; s++) {
            MBAR_INIT(base + s*8, 1);        // full[s]
            MBAR_INIT(base + 48 + s*8, 8);   // empty[s]
        }
    }
    __syncthreads();

#define LDGROW(r_, ccn_, va_, vb_) do { \
        int gy_ = y0 - 1 + (r_); \
        if ((unsigned)gy_ < 64u) { \
            const float* p_ = xin + (size_t)((b*CC + (ccn_)*32 + 2*pcp))*HW + gy_*WW + ppx; \
            va_ = *(const float4*)p_; \
            vb_ = *(const float4*)(p_ + HW); \
        } else { \
            va_ = make_float4(0.f,0.f,0.f,0.f); vb_ = make_float4(0.f,0.f,0.f,0.f); \
        } \
    } while (0)

#define STSROW(r_, ccn_, par_, va_, vb_) do { \
        float s0_ = smf[SM_STY + (ccn_)*32 + 2*pcp]; \
        float s1_ = smf[SM_STY + (ccn_)*32 + 2*pcp + 1]; \
        uint32_t* d_ = smu + SM_B0 + (par_)*B_BUF_U32 + pcp*B_K2STR + (r_)*B_ROWSTR + 2 + ppx; \
        ((uint2*)d_)[0] = make_uint2(packh2(va_.x*s0_, vb_.x*s1_), \
                                     packh2(va_.y*s0_, vb_.y*s1_)); \
        ((uint2*)(d_+2))[0] = make_uint2(packh2(va_.z*s0_, vb_.z*s1_), \
                                         packh2(va_.w*s0_, vb_.w*s1_)); \
    } while (0)

#define BULKA(c_, sl_) do { \
        int cc_ = (c_)/9, k_ = (c_) - cc_*9; \
        const uint32_t* src_ = g_Wf + (size_t)st*WF_STAGE + \
            (size_t)((k_*2 + ocsel)*8 + cc_)*A_CHUNK_U32; \
        uint32_t dst_ = base + (uint32_t)(SM_A0 + (sl_)*A_CHUNK_U32)*4u; \
        uint32_t mb_  = base + (uint32_t)((sl_)*8); \
        asm volatile("mbarrier.arrive.expect_tx.shared.b64 _, [%0], %1;" \
            :: "r"(mb_), "r"((uint32_t)A_CHUNK_BYTES) : "memory"); \
        asm volatile("cp.async.bulk.shared::cluster.global.mbarrier::complete_tx::bytes " \
            "[%0], [%1], %2, [%3];" \
            :: "r"(dst_), "l"(src_), "r"((uint32_t)A_CHUNK_BYTES), "r"(mb_) : "memory"); \
    } while (0)

    // initial B fill for cc=0 (6 rows, parity 0)
    {
        float4 t0, t1;
        #pragma unroll
        for (int r = 0; r < 6; r++) { LDGROW(r, 0, t0, t1); STSROW(r, 0, 0, t0, t1); }
    }
    if (tid == 0) {
        BULKA(0,0); BULKA(1,1); BULKA(2,2); BULKA(3,3); BULKA(4,4); BULKA(5,5);
    }
    __syncthreads();

    float acc[4][8][4];
    #pragma unroll
    for (int m = 0; m < 4; m++)
        #pragma unroll
        for (int n = 0; n < 8; n++)
            #pragma unroll
            for (int i = 0; i < 4; i++) acc[m][n][i] = 0.f;

    const int aidx = (woc*64 + (lane >> 2))*20 + (lane & 3);
    const int bofk = (lane & 3)*B_K2STR + (lane >> 2);

#define COMPUTE(k_, abuf_, bpar_) do { \
        const int dy_ = (k_)/3, dx_ = (k_) - dy_*3; \
        const uint32_t* A_ = smu + SM_A0 + (abuf_)*A_CHUNK_U32 + aidx; \
        const uint32_t* B_ = smu + SM_B0 + (bpar_)*B_BUF_U32 + (wn + dy_)*B_ROWSTR + dx_ + 1 + bofk; \
        _Pragma("unroll") \
        for (int ks = 0; ks < 2; ks++) { \
            uint32_t af[4][4]; \
            _Pragma("unroll") \
            for (int m = 0; m < 4; m++) { \
                const uint32_t* Am_ = A_ + m*320 + ks*8; \
                af[m][0] = Am_[0];   af[m][1] = Am_[160]; \
                af[m][2] = Am_[4];   af[m][3] = Am_[164]; \
            } \
            const uint32_t* Bk_ = B_ + ks*(8*B_K2STR); \
            _Pragma("unroll") \
            for (int nt = 0; nt < 8; nt++) { \
                uint32_t b0 = Bk_[nt*8]; \
                uint32_t b1 = Bk_[nt*8 + 4*B_K2STR]; \
                _Pragma("unroll") \
                for (int m = 0; m < 4; m++) \
                    MMA_F16(acc[m][nt], af[m][0], af[m][1], af[m][2], af[m][3], b0, b1); \
            } \
        } \
    } while (0)

    float4 ra0, ra1, rb0, rb1;

    #pragma unroll 1
    for (int cc = 0; cc < 8; cc++) {
        const int par = cc & 1;
        const int npar = par ^ 1;
        const int ccn = cc + 1;
        const bool more = (cc < 7);
        const int slotb = 3 * par;
        #pragma unroll
        for (int k = 0; k < 9; k++) {
            const int c = cc*9 + k;
            if (more) {
                if (k == 0) { LDGROW(0, ccn, ra0, ra1); }
                if (k == 1) { LDGROW(1, ccn, rb0, rb1); }
                if (k == 2) { __syncthreads();   // B parity swap guard
                              STSROW(0, ccn, npar, ra0, ra1);
                              STSROW(1, ccn, npar, rb0, rb1);
                              LDGROW(2, ccn, ra0, ra1);
                              LDGROW(3, ccn, rb0, rb1); }
                if (k == 4) { STSROW(2, ccn, npar, ra0, ra1);
                              STSROW(3, ccn, npar, rb0, rb1);
                              LDGROW(4, ccn, ra0, ra1);
                              LDGROW(5, ccn, rb0, rb1); }
                if (k == 6) { STSROW(4, ccn, npar, ra0, ra1);
                              STSROW(5, ccn, npar, rb0, rb1); }
            } else if (k == 2) {
                __syncthreads();
            }
            int sl = slotb + k; if (sl >= 6) sl -= 6;
            const int p6 = (c / 6) & 1;
            mbar_wait(base + sl*8, p6);
            COMPUTE(k, sl, par);
            if (lane == 0) MBAR_ARRIVE(base + 48 + sl*8);
            if (tid == 0 && c + 6 < 72) {
                mbar_wait(base + 48 + sl*8, p6);
                BULKA(c + 6, sl);
            }
        }
    }

#undef LDGROW
#undef STSROW
#undef BULKA
#undef COMPUTE

    // ---- epilogue: demod, noise, leaky ReLU ----
    const int y = y0 + wn;
    const int r = lane >> 2, tig = lane & 3;
    const float* dmp = g_demod + st*BB*CC;
    #pragma unroll
    for (int m = 0; m < 4; m++) {
        const int ocA = oc0 + woc*64 + m*16 + r;
        const int ocB = ocA + 8;
        const float dA = __ldg(&dmp[b*CC + ocA]);
        const float dB = __ldg(&dmp[b*CC + ocB]);
        const float nA = __ldg(&nw[ocA]);
        const float nB = __ldg(&nw[ocB]);
        #pragma unroll
        for (int nt = 0; nt < 8; nt++) {
            const int col = nt*8 + tig*2;
            const float2 nz = *(const float2*)(noise + (size_t)b*HW + y*WW + col);
            float v0 = acc[m][nt][0]*dA + nA*nz.x;
            float v1 = acc[m][nt][1]*dA + nA*nz.y;
            float v2 = acc[m][nt][2]*dB + nB*nz.x;
            float v3 = acc[m][nt][3]*dB + nB*nz.y;
            v0 = v0 > 0.f ? v0 : 0.2f*v0;
            v1 = v1 > 0.f ? v1 : 0.2f*v1;
            v2 = v2 > 0.f ? v2 : 0.2f*v2;
            v3 = v3 > 0.f ? v3 : 0.2f*v3;
            *(float2*)(outp + (size_t)(b*CC + ocA)*HW + y*WW + col) = make_float2(v0, v1);
            *(float2*)(outp + (size_t)(b*CC + ocB)*HW + y*WW + col) = make_float2(v2, v3);
        }
    }
}

// ---------------------------------------------------------------------------
extern "C" void kernel_launch(void* const* d_in, const int* in_sizes, int n_in,
                              void* d_out, int out_size) {
    const float* x   = (const float*)d_in[0];
    const float* w1  = (const float*)d_in[1];
    const float* w2  = (const float*)d_in[2];
    const float* n1  = (const float*)d_in[3];
    const float* n2  = (const float*)d_in[4];
    const float* s1w = (const float*)d_in[5];
    const float* s1b = (const float*)d_in[6];
    const float* c1w = (const float*)d_in[7];
    const float* nw1 = (const float*)d_in[8];
    const float* s2w = (const float*)d_in[9];
    const float* s2b = (const float*)d_in[10];
    const float* c2w = (const float*)d_in[11];
    const float* nw2 = (const float*)d_in[12];
    float* out = (float*)d_out;

    static int configured = 0;
    if (!configured) {
        cudaFuncSetAttribute(k_conv, cudaFuncAttributeMaxDynamicSharedMemorySize, SM_BYTES);
        configured = 1;
    }

    dim3 cgrid(16, 2, BB);       // 16 row-quads x 2 oc halves x 16 batches
    dim3 dgrid(BB, 1, 2);

    k_prep <<<928, 256>>>(w1, s1w, s1b, c1w, w2, s2w, s2b, c2w);
    k_demod<<<dgrid, 256>>>();

    k_conv <<<cgrid, 256, SM_BYTES>>>(x, out, n1, nw1, 0);
    k_conv <<<cgrid, 256, SM_BYTES>>>(x, out, n2, nw2, 1);
}

// round 13
// speedup vs baseline: 1.0009x; 1.0009x over previous
#include <cuda_runtime.h>
#include <cuda_fp16.h>
#include <cstdint>

#define BB 16
#define CC 256
#define HH 64
#define WW 64
#define SSD 512
#define HW 4096

// A chunk image (fp16 pairs): [128 oc rows][20 u32 words]; word j = ci pair (2j,2j+1), j<16; 4 pad
#define A_CHUNK_U32   2560
#define A_CHUNK_BYTES 10240
#define N_ABUF 6
#define WF_STAGE (9*2*8*A_CHUNK_U32)

// B buffer (fp16 pairs): [16 k2 words][6 rows][68 slots]; slot = col+2 (0,1,66,67 zero)
#define B_K2STR 408            // 6*68 ; 408 mod 32 = 24 -> conflict-free b-frags
#define B_ROWSTR 68
#define B_BUF_U32 (16*B_K2STR) // 6528

// smem u32 map: [0..96B) 12 mbars, styles at u32 24
#define SM_STY 24
#define SM_A0  288
#define SM_B0  (288 + N_ABUF*A_CHUNK_U32)   // 15648
#define SM_U32 (SM_B0 + 2*B_BUF_U32)        // 28704
#define SM_BYTES (SM_U32*4)                 // 114816

__device__ float    g_inter[BB*CC*HW];
__device__ float    g_style[2*BB*CC];
__device__ float    g_demod[2*BB*CC];
__device__ float    g_Rt[2*CC*CC];
__device__ uint32_t g_Wf[2*WF_STAGE];

// ---------------- helpers ----------------
__device__ __forceinline__ uint32_t smem_u32(const void* p) {
    uint32_t a;
    asm("{ .reg .u64 t; cvta.to.shared.u64 t, %1; cvt.u32.u64 %0, t; }" : "=r"(a) : "l"(p));
    return a;
}
__device__ __forceinline__ uint32_t packh2(float lo, float hi) {
    __half2 h = __floats2half2_rn(lo, hi);
    return *(uint32_t*)&h;
}
__device__ __forceinline__ void mbar_wait(uint32_t mbar, uint32_t parity) {
    asm volatile(
        "{\n\t.reg .pred P;\n\t"
        "WL_%=:\n\t"
        "mbarrier.try_wait.parity.acquire.cta.shared::cta.b64 P, [%0], %1, 0x989680;\n\t"
        "@P bra.uni WD_%=;\n\t"
        "bra.uni WL_%=;\n\t"
        "WD_%=:\n\t}"
        :: "r"(mbar), "r"(parity) : "memory");
}
#define MBAR_INIT(a,n)  asm volatile("mbarrier.init.shared.b64 [%0], %1;" :: "r"(a), "r"((uint32_t)(n)) : "memory")
#define MBAR_ARRIVE(a)  asm volatile("mbarrier.arrive.release.cta.shared::cta.b64 _, [%0];" :: "r"(a) : "memory")

#define MMA_F16(d, a0,a1,a2,a3, b0,b1) \
    asm volatile("mma.sync.aligned.m16n8k16.row.col.f32.f16.f16.f32 " \
        "{%0,%1,%2,%3}, {%4,%5,%6,%7}, {%8,%9}, {%0,%1,%2,%3};" \
        : "+f"((d)[0]), "+f"((d)[1]), "+f"((d)[2]), "+f"((d)[3]) \
        : "r"(a0), "r"(a1), "r"(a2), "r"(a3), "r"(b0), "r"(b1))

// ---------------- fused prep (style + Rt + Wf) via flat grid ----------------
// blocks 0..127: style (st,b,chgrp) ; 128..639: Rt (st,ci) ; 640..927: Wf
__global__ void k_prep(const float* __restrict__ w1v, const float* __restrict__ s1w,
                       const float* __restrict__ s1b, const float* __restrict__ c1w,
                       const float* __restrict__ w2v, const float* __restrict__ s2w,
                       const float* __restrict__ s2b, const float* __restrict__ c2w) {
    __shared__ float s[SSD];
    const int bid = blockIdx.x, t = threadIdx.x;

    if (bid < 128) {
        const int st = bid >> 6, rem = bid & 63;
        const int b = rem & 15, chgrp = rem >> 4;
        const float* wv = st ? w2v : w1v;
        const float* sw = st ? s2w : s1w;
        const float* sb = st ? s2b : s1b;
        s[t] = wv[b*SSD + t]; s[t+256] = wv[b*SSD + 256 + t];
        __syncthreads();
        const int ch   = chgrp*64 + (t >> 2);
        const int part = t & 3;
        float acc = 0.f;
        const float* rw = sw + (size_t)ch*SSD + part*128;
        const float* sp = s + part*128;
        #pragma unroll 8
        for (int j = 0; j < 128; j++) acc += sp[j] * rw[j];
        acc += __shfl_xor_sync(0xFFFFFFFF, acc, 1);
        acc += __shfl_xor_sync(0xFFFFFFFF, acc, 2);
        if (part == 0) g_style[st*BB*CC + b*CC + ch] = acc * 0.03125f + sb[ch];
    } else if (bid < 640) {
        const int idx = bid - 128;
        const int st = idx >> 8, ci = idx & 255;
        const float* w = st ? c2w : c1w;
        const float* src = w + (t*CC + ci)*9;
        float s2 = 0.f;
        #pragma unroll
        for (int k = 0; k < 9; k++) { float v = src[k]; s2 += v*v; }
        g_Rt[st*CC*CC + ci*CC + t] = s2;
    } else {
        const int idx = bid - 640;           // 0..287
        const int k = idx % 9, r = idx / 9;  // r: 0..31
        const int oh = r & 1, cc = (r >> 1) & 7, st = r >> 4;
        const float* w = st ? c2w : c1w;
        uint32_t* dst = g_Wf + (size_t)st*WF_STAGE + (size_t)((k*2 + oh)*8 + cc)*A_CHUNK_U32;
        for (int f = t; f < A_CHUNK_U32; f += 256) {
            const int row = f / 20;
            const int j   = f - row*20;
            uint32_t v = 0;
            if (j < 16) {
                const size_t rb = (size_t)((oh*128 + row)*CC + cc*32 + 2*j)*9 + k;
                v = packh2(w[rb], w[rb + 9]);
            }
            dst[f] = v;
        }
    }
}

// coalesced demod: thread = channel, row-major Rt scan
__global__ void k_demod() {
    const int st = blockIdx.z, b = blockIdx.x, t = threadIdx.x;
    __shared__ float st2[CC];
    float s = g_style[st*BB*CC + b*CC + t];
    st2[t] = s*s;
    __syncthreads();
    const float* rt = g_Rt + st*CC*CC + t;
    float acc = 0.f;
    #pragma unroll 8
    for (int i = 0; i < CC; i++) acc += st2[i] * rt[(size_t)i*CC];
    g_demod[st*BB*CC + b*CC + t] = rsqrtf(acc + 1e-8f);
}

// ---------------- fp16 mma.sync implicit-GEMM conv ----------------
// CTA: M=128 oc x N=256 px (4 image rows). 8 warps = 2 Mwarps x 4 Nwarps,
// warp tile 64x64. K = 2304 in 72 chunks (2 x m16n8k16 per ks, 64 MMA/warp).
// A: 6-slot cp.async.bulk ring (full tx-mbars + empty 8-arrival mbars);
// B: 6 input rows per cc, double-buffered, one __syncthreads per cc.
__global__ __launch_bounds__(256, 1)
void k_conv(const float* __restrict__ xg, float* __restrict__ outg,
            const float* __restrict__ noise, const float* __restrict__ nw,
            int st) {
    extern __shared__ uint32_t smu[];
    float* smf = (float*)smu;
    const uint32_t base = smem_u32(smu);

    const float* xin  = (st == 0) ? xg : g_inter;
    float*       outp = (st == 0) ? g_inter : outg;

    const int tid = threadIdx.x, wid = tid >> 5, lane = tid & 31;
    const int woc = wid & 1;                 // M half (64 oc)
    const int wn  = wid >> 1;                // output row 0..3
    const int y0  = blockIdx.x * 4;
    const int ocsel = blockIdx.y;
    const int oc0 = ocsel * 128;
    const int b   = blockIdx.z;

    const int pcp = tid >> 4;          // ci pair 0..15
    const int ppx = (tid & 15) * 4;    // px 0..60

    // zero only the boundary slots (0,1,66,67) of both B buffers
    for (int i = tid; i < 768; i += 256) {
        const int buf = i / 384, rem = i - buf*384;
        const int line = rem >> 2, q = rem & 3;
        const int k2 = line / 6, row = line - k2*6;
        const int slot = (q < 2) ? q : (64 + q);
        smu[SM_B0 + buf*B_BUF_U32 + k2*B_K2STR + row*B_ROWSTR + slot] = 0;
    }
    smf[SM_STY + tid] = g_style[st*BB*CC + b*CC + tid];
    if (tid == 0) {
        #pragma unroll
        for (int s = 0; s < 6; s++) {
            MBAR_INIT(base + s*8, 1);        // full[s]
            MBAR_INIT(base + 48 + s*8, 8);   // empty[s]
        }
    }
    __syncthreads();

#define LDGROW(r_, ccn_, va_, vb_) do { \
        int gy_ = y0 - 1 + (r_); \
        if ((unsigned)gy_ < 64u) { \
            const float* p_ = xin + (size_t)((b*CC + (ccn_)*32 + 2*pcp))*HW + gy_*WW + ppx; \
            va_ = *(const float4*)p_; \
            vb_ = *(const float4*)(p_ + HW); \
        } else { \
            va_ = make_float4(0.f,0.f,0.f,0.f); vb_ = make_float4(0.f,0.f,0.f,0.f); \
        } \
    } while (0)

#define STSROW(r_, ccn_, par_, va_, vb_) do { \
        float s0_ = smf[SM_STY + (ccn_)*32 + 2*pcp]; \
        float s1_ = smf[SM_STY + (ccn_)*32 + 2*pcp + 1]; \
        uint32_t* d_ = smu + SM_B0 + (par_)*B_BUF_U32 + pcp*B_K2STR + (r_)*B_ROWSTR + 2 + ppx; \
        ((uint2*)d_)[0] = make_uint2(packh2(va_.x*s0_, vb_.x*s1_), \
                                     packh2(va_.y*s0_, vb_.y*s1_)); \
        ((uint2*)(d_+2))[0] = make_uint2(packh2(va_.z*s0_, vb_.z*s1_), \
                                         packh2(va_.w*s0_, vb_.w*s1_)); \
    } while (0)

#define BULKA(c_, sl_) do { \
        int cc_ = (c_)/9, k_ = (c_) - cc_*9; \
        const uint32_t* src_ = g_Wf + (size_t)st*WF_STAGE + \
            (size_t)((k_*2 + ocsel)*8 + cc_)*A_CHUNK_U32; \
        uint32_t dst_ = base + (uint32_t)(SM_A0 + (sl_)*A_CHUNK_U32)*4u; \
        uint32_t mb_  = base + (uint32_t)((sl_)*8); \
        asm volatile("mbarrier.arrive.expect_tx.shared.b64 _, [%0], %1;" \
            :: "r"(mb_), "r"((uint32_t)A_CHUNK_BYTES) : "memory"); \
        asm volatile("cp.async.bulk.shared::cluster.global.mbarrier::complete_tx::bytes " \
            "[%0], [%1], %2, [%3];" \
            :: "r"(dst_), "l"(src_), "r"((uint32_t)A_CHUNK_BYTES), "r"(mb_) : "memory"); \
    } while (0)

    // initial B fill for cc=0 (6 rows, parity 0)
    {
        float4 t0, t1;
        #pragma unroll
        for (int r = 0; r < 6; r++) { LDGROW(r, 0, t0, t1); STSROW(r, 0, 0, t0, t1); }
    }
    if (tid == 0) {
        BULKA(0,0); BULKA(1,1); BULKA(2,2); BULKA(3,3); BULKA(4,4); BULKA(5,5);
    }
    __syncthreads();

    float acc[4][8][4];
    #pragma unroll
    for (int m = 0; m < 4; m++)
        #pragma unroll
        for (int n = 0; n < 8; n++)
            #pragma unroll
            for (int i = 0; i < 4; i++) acc[m][n][i] = 0.f;

    const int aidx = (woc*64 + (lane >> 2))*20 + (lane & 3);
    const int bofk = (lane & 3)*B_K2STR + (lane >> 2);

#define COMPUTE(k_, abuf_, bpar_) do { \
        const int dy_ = (k_)/3, dx_ = (k_) - dy_*3; \
        const uint32_t* A_ = smu + SM_A0 + (abuf_)*A_CHUNK_U32 + aidx; \
        const uint32_t* B_ = smu + SM_B0 + (bpar_)*B_BUF_U32 + (wn + dy_)*B_ROWSTR + dx_ + 1 + bofk; \
        _Pragma("unroll") \
        for (int ks = 0; ks < 2; ks++) { \
            uint32_t af[4][4]; \
            _Pragma("unroll") \
            for (int m = 0; m < 4; m++) { \
                const uint32_t* Am_ = A_ + m*320 + ks*8; \
                af[m][0] = Am_[0];   af[m][1] = Am_[160]; \
                af[m][2] = Am_[4];   af[m][3] = Am_[164]; \
            } \
            const uint32_t* Bk_ = B_ + ks*(8*B_K2STR); \
            _Pragma("unroll") \
            for (int nt = 0; nt < 8; nt++) { \
                uint32_t b0 = Bk_[nt*8]; \
                uint32_t b1 = Bk_[nt*8 + 4*B_K2STR]; \
                _Pragma("unroll") \
                for (int m = 0; m < 4; m++) \
                    MMA_F16(acc[m][nt], af[m][0], af[m][1], af[m][2], af[m][3], b0, b1); \
            } \
        } \
    } while (0)

    float4 ra0, ra1, rb0, rb1;

    #pragma unroll 1
    for (int cc = 0; cc < 8; cc++) {
        const int par = cc & 1;
        const int npar = par ^ 1;
        const int ccn = cc + 1;
        const bool more = (cc < 7);
        const int slotb = 3 * par;
        #pragma unroll
        for (int k = 0; k < 9; k++) {
            const int c = cc*9 + k;
            if (more) {
                if (k == 0) { LDGROW(0, ccn, ra0, ra1); }
                if (k == 1) { LDGROW(1, ccn, rb0, rb1); }
                if (k == 2) { __syncthreads();   // B parity swap guard
                              STSROW(0, ccn, npar, ra0, ra1);
                              STSROW(1, ccn, npar, rb0, rb1);
                              LDGROW(2, ccn, ra0, ra1);
                              LDGROW(3, ccn, rb0, rb1); }
                if (k == 4) { STSROW(2, ccn, npar, ra0, ra1);
                              STSROW(3, ccn, npar, rb0, rb1);
                              LDGROW(4, ccn, ra0, ra1);
                              LDGROW(5, ccn, rb0, rb1); }
                if (k == 6) { STSROW(4, ccn, npar, ra0, ra1);
                              STSROW(5, ccn, npar, rb0, rb1); }
            } else if (k == 2) {
                __syncthreads();
            }
            int sl = slotb + k; if (sl >= 6) sl -= 6;
            const int p6 = (c / 6) & 1;
            mbar_wait(base + sl*8, p6);
            COMPUTE(k, sl, par);
            if (lane == 0) MBAR_ARRIVE(base + 48 + sl*8);
            if (tid == 0 && c + 6 < 72) {
                mbar_wait(base + 48 + sl*8, p6);
                BULKA(c + 6, sl);
            }
        }
    }

#undef LDGROW
#undef STSROW
#undef BULKA
#undef COMPUTE

    // ---- epilogue: demod, noise, leaky ReLU ----
    const int y = y0 + wn;
    const int r = lane >> 2, tig = lane & 3;
    const float* dmp = g_demod + st*BB*CC;
    #pragma unroll
    for (int m = 0; m < 4; m++) {
        const int ocA = oc0 + woc*64 + m*16 + r;
        const int ocB = ocA + 8;
        const float dA = __ldg(&dmp[b*CC + ocA]);
        const float dB = __ldg(&dmp[b*CC + ocB]);
        const float nA = __ldg(&nw[ocA]);
        const float nB = __ldg(&nw[ocB]);
        #pragma unroll
        for (int nt = 0; nt < 8; nt++) {
            const int col = nt*8 + tig*2;
            const float2 nz = *(const float2*)(noise + (size_t)b*HW + y*WW + col);
            float v0 = acc[m][nt][0]*dA + nA*nz.x;
            float v1 = acc[m][nt][1]*dA + nA*nz.y;
            float v2 = acc[m][nt][2]*dB + nB*nz.x;
            float v3 = acc[m][nt][3]*dB + nB*nz.y;
            v0 = v0 > 0.f ? v0 : 0.2f*v0;
            v1 = v1 > 0.f ? v1 : 0.2f*v1;
            v2 = v2 > 0.f ? v2 : 0.2f*v2;
            v3 = v3 > 0.f ? v3 : 0.2f*v3;
            *(float2*)(outp + (size_t)(b*CC + ocA)*HW + y*WW + col) = make_float2(v0, v1);
            *(float2*)(outp + (size_t)(b*CC + ocB)*HW + y*WW + col) = make_float2(v2, v3);
        }
    }
}

// ---------------------------------------------------------------------------
extern "C" void kernel_launch(void* const* d_in, const int* in_sizes, int n_in,
                              void* d_out, int out_size) {
    const float* x   = (const float*)d_in[0];
    const float* w1  = (const float*)d_in[1];
    const float* w2  = (const float*)d_in[2];
    const float* n1  = (const float*)d_in[3];
    const float* n2  = (const float*)d_in[4];
    const float* s1w = (const float*)d_in[5];
    const float* s1b = (const float*)d_in[6];
    const float* c1w = (const float*)d_in[7];
    const float* nw1 = (const float*)d_in[8];
    const float* s2w = (const float*)d_in[9];
    const float* s2b = (const float*)d_in[10];
    const float* c2w = (const float*)d_in[11];
    const float* nw2 = (const float*)d_in[12];
    float* out = (float*)d_out;

    static int configured = 0;
    if (!configured) {
        cudaFuncSetAttribute(k_conv, cudaFuncAttributeMaxDynamicSharedMemorySize, SM_BYTES);
        configured = 1;
    }

    dim3 cgrid(16, 2, BB);       // 16 row-quads x 2 oc halves x 16 batches
    dim3 dgrid(BB, 1, 2);

    k_prep <<<928, 256>>>(w1, s1w, s1b, c1w, w2, s2w, s2b, c2w);
    k_demod<<<dgrid, 256>>>();

    k_conv <<<cgrid, 256, SM_BYTES>>>(x, out, n1, nw1, 0);
    k_conv <<<cgrid, 256, SM_BYTES>>>(x, out, n2, nw2, 1);
}

// round 16
// speedup vs baseline: 1.0888x; 1.0879x over previous
#include <cuda_runtime.h>
#include <cuda_fp16.h>
#include <cstdint>

#define BB 16
#define CC 256
#define HH 64
#define WW 64
#define SSD 512
#define HW 4096

// A chunk image (fp16 pairs): [128 oc rows][20 u32 words]; word j = ci pair (2j,2j+1), j<16; 4 pad
#define A_CHUNK_U32   2560
#define A_CHUNK_BYTES 10240
#define N_ABUF 6
#define WF_STAGE (9*2*8*A_CHUNK_U32)

// B buffer (fp16 pairs): [16 k2 words][4 rows][68 slots]; slot = col+2 (0,1,66,67 zero)
#define B_K2STR 280            // 4*68 + 8 pad ; 280 mod 32 = 24 -> conflict-free b-frags
#define B_ROWSTR 68
#define B_BUF_U32 (16*B_K2STR) // 4480

// smem u32 map: bytes [0..48) A-full mbars, [48..96) A-empty mbars; styles @ u32 24
#define SM_STY 24
#define SM_A0  288
#define SM_B0  (288 + N_ABUF*A_CHUNK_U32)   // 15648
#define SM_U32 (SM_B0 + 2*B_BUF_U32)        // 24608
#define SM_BYTES (SM_U32*4)                 // 98432

__device__ float    g_inter[BB*CC*HW];
__device__ float    g_style[2*BB*CC];
__device__ float    g_demod[2*BB*CC];
__device__ float    g_Rt[2*CC*CC];
__device__ uint32_t g_Wf[2*WF_STAGE];

// ---------------- helpers ----------------
__device__ __forceinline__ uint32_t smem_u32(const void* p) {
    uint32_t a;
    asm("{ .reg .u64 t; cvta.to.shared.u64 t, %1; cvt.u32.u64 %0, t; }" : "=r"(a) : "l"(p));
    return a;
}
__device__ __forceinline__ uint32_t packh2(float lo, float hi) {
    __half2 h = __floats2half2_rn(lo, hi);
    return *(uint32_t*)&h;
}
__device__ __forceinline__ void mbar_wait(uint32_t mbar, uint32_t parity) {
    asm volatile(
        "{\n\t.reg .pred P;\n\t"
        "WL_%=:\n\t"
        "mbarrier.try_wait.parity.acquire.cta.shared::cta.b64 P, [%0], %1, 0x989680;\n\t"
        "@P bra.uni WD_%=;\n\t"
        "bra.uni WL_%=;\n\t"
        "WD_%=:\n\t}"
        :: "r"(mbar), "r"(parity) : "memory");
}
#define MBAR_INIT(a,n)  asm volatile("mbarrier.init.shared.b64 [%0], %1;" :: "r"(a), "r"((uint32_t)(n)) : "memory")
#define MBAR_ARRIVE(a)  asm volatile("mbarrier.arrive.release.cta.shared::cta.b64 _, [%0];" :: "r"(a) : "memory")

#define MMA_F16(d, a0,a1,a2,a3, b0,b1) \
    asm volatile("mma.sync.aligned.m16n8k16.row.col.f32.f16.f16.f32 " \
        "{%0,%1,%2,%3}, {%4,%5,%6,%7}, {%8,%9}, {%0,%1,%2,%3};" \
        : "+f"((d)[0]), "+f"((d)[1]), "+f"((d)[2]), "+f"((d)[3]) \
        : "r"(a0), "r"(a1), "r"(a2), "r"(a3), "r"(b0), "r"(b1))

// ---------------- fused prep (style + Rt + Wf) via flat grid ----------------
__global__ void k_prep(const float* __restrict__ w1v, const float* __restrict__ s1w,
                       const float* __restrict__ s1b, const float* __restrict__ c1w,
                       const float* __restrict__ w2v, const float* __restrict__ s2w,
                       const float* __restrict__ s2b, const float* __restrict__ c2w) {
    __shared__ float s[SSD];
    const int bid = blockIdx.x, t = threadIdx.x;

    if (bid < 128) {
        const int st = bid >> 6, rem = bid & 63;
        const int b = rem & 15, chgrp = rem >> 4;
        const float* wv = st ? w2v : w1v;
        const float* sw = st ? s2w : s1w;
        const float* sb = st ? s2b : s1b;
        s[t] = wv[b*SSD + t]; s[t+256] = wv[b*SSD + 256 + t];
        __syncthreads();
        const int ch   = chgrp*64 + (t >> 2);
        const int part = t & 3;
        float acc = 0.f;
        const float* rw = sw + (size_t)ch*SSD + part*128;
        const float* sp = s + part*128;
        #pragma unroll 8
        for (int j = 0; j < 128; j++) acc += sp[j] * rw[j];
        acc += __shfl_xor_sync(0xFFFFFFFF, acc, 1);
        acc += __shfl_xor_sync(0xFFFFFFFF, acc, 2);
        if (part == 0) g_style[st*BB*CC + b*CC + ch] = acc * 0.03125f + sb[ch];
    } else if (bid < 640) {
        const int idx = bid - 128;
        const int st = idx >> 8, ci = idx & 255;
        const float* w = st ? c2w : c1w;
        const float* src = w + (t*CC + ci)*9;
        float s2 = 0.f;
        #pragma unroll
        for (int k = 0; k < 9; k++) { float v = src[k]; s2 += v*v; }
        g_Rt[st*CC*CC + ci*CC + t] = s2;
    } else {
        const int idx = bid - 640;           // 0..287
        const int k = idx % 9, r = idx / 9;  // r: 0..31
        const int oh = r & 1, cc = (r >> 1) & 7, st = r >> 4;
        const float* w = st ? c2w : c1w;
        uint32_t* dst = g_Wf + (size_t)st*WF_STAGE + (size_t)((k*2 + oh)*8 + cc)*A_CHUNK_U32;
        for (int f = t; f < A_CHUNK_U32; f += 256) {
            const int row = f / 20;
            const int j   = f - row*20;
            uint32_t v = 0;
            if (j < 16) {
                const size_t rb = (size_t)((oh*128 + row)*CC + cc*32 + 2*j)*9 + k;
                v = packh2(w[rb], w[rb + 9]);
            }
            dst[f] = v;
        }
    }
}

// coalesced demod: thread = channel, row-major Rt scan
__global__ void k_demod() {
    const int st = blockIdx.z, b = blockIdx.x, t = threadIdx.x;
    __shared__ float st2[CC];
    float s = g_style[st*BB*CC + b*CC + t];
    st2[t] = s*s;
    __syncthreads();
    const float* rt = g_Rt + st*CC*CC + t;
    float acc = 0.f;
    #pragma unroll 8
    for (int i = 0; i < CC; i++) acc += st2[i] * rt[(size_t)i*CC];
    g_demod[st*BB*CC + b*CC + t] = rsqrtf(acc + 1e-8f);
}

// ---------------- fp16 mma.sync implicit-GEMM conv ----------------
// CTA: M=128 oc x N=128 px (2 image rows), 128 threads = 4 warps
// (woc=wid&1 -> 64 oc, wn=wid>>1 -> output row), warp tile 64x64.
// 2 CTAs/SM: independent co-tenants hide each other's barrier/mbar stalls.
// K = 2304 in 72 chunks; A: 6-slot cp.async.bulk ring (full tx-mbars +
// empty 4-arrival mbars, refill distributed over warps); B: 4 input rows
// per cc, double-buffered, one __syncthreads per cc.
__global__ __launch_bounds__(128, 2)
void k_conv(const float* __restrict__ xg, float* __restrict__ outg,
            const float* __restrict__ noise, const float* __restrict__ nw,
            int st) {
    extern __shared__ uint32_t smu[];
    float* smf = (float*)smu;
    const uint32_t base = smem_u32(smu);

    const float* xin  = (st == 0) ? xg : g_inter;
    float*       outp = (st == 0) ? g_inter : outg;

    const int tid = threadIdx.x, wid = tid >> 5, lane = tid & 31;
    const int woc = wid & 1;                 // M half (64 oc)
    const int wn  = wid >> 1;                // output row 0..1
    const int y0  = blockIdx.x * 2;
    const int ocsel = blockIdx.y;
    const int oc0 = ocsel * 128;
    const int b   = blockIdx.z;

    const int pcp = tid >> 3;          // ci pair 0..15
    const int pq  = tid & 7;           // px octet (8 px)

    // zero only the boundary slots (0,1,66,67) of both B buffers
    for (int i = tid; i < 512; i += 128) {
        const int buf = i >> 8, rem = i & 255;
        const int line = rem >> 2, q = rem & 3;
        const int k2 = line >> 2, row = line & 3;
        const int slot = (q < 2) ? q : (64 + q);
        smu[SM_B0 + buf*B_BUF_U32 + k2*B_K2STR + row*B_ROWSTR + slot] = 0;
    }
    for (int i = tid; i < CC; i += 128)
        smf[SM_STY + i] = g_style[st*BB*CC + b*CC + i];
    if (tid == 0) {
        #pragma unroll
        for (int s = 0; s < 6; s++) {
            MBAR_INIT(base + s*8, 1);        // full[s] (tx)
            MBAR_INIT(base + 48 + s*8, 4);   // empty[s] (4 warp arrivals)
        }
    }
    __syncthreads();

    float4 ra0, ra1, rb0, rb1;   // one B row in flight (ci pair x 8 px)

#define LDGROW(r_, ccn_) do { \
        int gy_ = y0 - 1 + (r_); \
        if ((unsigned)gy_ < 64u) { \
            const float* p_ = xin + (size_t)((b*CC + (ccn_)*32 + 2*pcp))*HW + gy_*WW + pq*8; \
            ra0 = *(const float4*)p_;        ra1 = *(const float4*)(p_ + 4); \
            rb0 = *(const float4*)(p_ + HW); rb1 = *(const float4*)(p_ + HW + 4); \
        } else { \
            ra0 = ra1 = rb0 = rb1 = make_float4(0.f,0.f,0.f,0.f); \
        } \
    } while (0)

#define STSROW(r_, ccn_, par_) do { \
        float s0_ = smf[SM_STY + (ccn_)*32 + 2*pcp]; \
        float s1_ = smf[SM_STY + (ccn_)*32 + 2*pcp + 1]; \
        uint32_t* d_ = smu + SM_B0 + (par_)*B_BUF_U32 + pcp*B_K2STR + (r_)*B_ROWSTR + 2 + pq*8; \
        ((uint2*)d_)[0]     = make_uint2(packh2(ra0.x*s0_, rb0.x*s1_), packh2(ra0.y*s0_, rb0.y*s1_)); \
        ((uint2*)(d_+2))[0] = make_uint2(packh2(ra0.z*s0_, rb0.z*s1_), packh2(ra0.w*s0_, rb0.w*s1_)); \
        ((uint2*)(d_+4))[0] = make_uint2(packh2(ra1.x*s0_, rb1.x*s1_), packh2(ra1.y*s0_, rb1.y*s1_)); \
        ((uint2*)(d_+6))[0] = make_uint2(packh2(ra1.z*s0_, rb1.z*s1_), packh2(ra1.w*s0_, rb1.w*s1_)); \
    } while (0)

#define BULKA(c_, sl_) do { \
        int cc_ = (c_)/9, k_ = (c_) - cc_*9; \
        const uint32_t* src_ = g_Wf + (size_t)st*WF_STAGE + \
            (size_t)((k_*2 + ocsel)*8 + cc_)*A_CHUNK_U32; \
        uint32_t dst_ = base + (uint32_t)(SM_A0 + (sl_)*A_CHUNK_U32)*4u; \
        uint32_t mb_  = base + (uint32_t)((sl_)*8); \
        asm volatile("mbarrier.arrive.expect_tx.shared.b64 _, [%0], %1;" \
            :: "r"(mb_), "r"((uint32_t)A_CHUNK_BYTES) : "memory"); \
        asm volatile("cp.async.bulk.shared::cluster.global.mbarrier::complete_tx::bytes " \
            "[%0], [%1], %2, [%3];" \
            :: "r"(dst_), "l"(src_), "r"((uint32_t)A_CHUNK_BYTES), "r"(mb_) : "memory"); \
    } while (0)

    // initial B fill for cc=0 (4 rows, parity 0)
    #pragma unroll
    for (int r = 0; r < 4; r++) { LDGROW(r, 0); STSROW(r, 0, 0); }
    if (tid == 0) {
        BULKA(0,0); BULKA(1,1); BULKA(2,2); BULKA(3,3); BULKA(4,4); BULKA(5,5);
    }
    __syncthreads();

    float acc[4][8][4];
    #pragma unroll
    for (int m = 0; m < 4; m++)
        #pragma unroll
        for (int n = 0; n < 8; n++)
            #pragma unroll
            for (int i = 0; i < 4; i++) acc[m][n][i] = 0.f;

    const int aidx = (woc*64 + (lane >> 2))*20 + (lane & 3);
    const int bofk = (lane & 3)*B_K2STR + (lane >> 2);

#define COMPUTE(k_, abuf_, bpar_) do { \
        const int dy_ = (k_)/3, dx_ = (k_) - dy_*3; \
        const uint32_t* A_ = smu + SM_A0 + (abuf_)*A_CHUNK_U32 + aidx; \
        const uint32_t* B_ = smu + SM_B0 + (bpar_)*B_BUF_U32 + (wn + dy_)*B_ROWSTR + dx_ + 1 + bofk; \
        _Pragma("unroll") \
        for (int ks = 0; ks < 2; ks++) { \
            uint32_t af[4][4]; \
            _Pragma("unroll") \
            for (int m = 0; m < 4; m++) { \
                const uint32_t* Am_ = A_ + m*320 + ks*8; \
                af[m][0] = Am_[0];   af[m][1] = Am_[160]; \
                af[m][2] = Am_[4];   af[m][3] = Am_[164]; \
            } \
            const uint32_t* Bk_ = B_ + ks*(8*B_K2STR); \
            _Pragma("unroll") \
            for (int nt = 0; nt < 8; nt++) { \
                uint32_t b0 = Bk_[nt*8]; \
                uint32_t b1 = Bk_[nt*8 + 4*B_K2STR]; \
                _Pragma("unroll") \
                for (int m = 0; m < 4; m++) \
                    MMA_F16(acc[m][nt], af[m][0], af[m][1], af[m][2], af[m][3], b0, b1); \
            } \
        } \
    } while (0)

    #pragma unroll 1
    for (int cc = 0; cc < 8; cc++) {
        const int par = cc & 1;
        const int npar = par ^ 1;
        const int ccn = cc + 1;
        const bool more = (cc < 7);
        const int slotb = 3 * par;           // (9*cc) % 6
        #pragma unroll
        for (int k = 0; k < 9; k++) {
            const int c = cc*9 + k;
            if (k == 2) __syncthreads();     // B parity swap guard (co-tenant hides)
            if (more) {
                if (k == 0) LDGROW(0, ccn);
                if (k == 2) { STSROW(0, ccn, npar); LDGROW(1, ccn); }
                if (k == 3) { STSROW(1, ccn, npar); LDGROW(2, ccn); }
                if (k == 4) { STSROW(2, ccn, npar); LDGROW(3, ccn); }
                if (k == 5) { STSROW(3, ccn, npar); }
            }
            int sl = slotb + k; if (sl >= 6) sl -= 6;
            const int p6 = (c / 6) & 1;
            mbar_wait(base + sl*8, p6);
            COMPUTE(k, sl, par);
            if (lane == 0) MBAR_ARRIVE(base + 48 + sl*8);
            if (wid == (sl & 3) && lane == 0 && c + 6 < 72) {
                mbar_wait(base + 48 + sl*8, p6);   // all 4 warps done with slot
                BULKA(c + 6, sl);
            }
        }
    }

#undef LDGROW
#undef STSROW
#undef BULKA
#undef COMPUTE

    // ---- epilogue: demod, noise, leaky ReLU ----
    const int y = y0 + wn;
    const int r = lane >> 2, tig = lane & 3;
    const float* dmp = g_demod + st*BB*CC;
    #pragma unroll
    for (int m = 0; m < 4; m++) {
        const int ocA = oc0 + woc*64 + m*16 + r;
        const int ocB = ocA + 8;
        const float dA = __ldg(&dmp[b*CC + ocA]);
        const float dB = __ldg(&dmp[b*CC + ocB]);
        const float nA = __ldg(&nw[ocA]);
        const float nB = __ldg(&nw[ocB]);
        #pragma unroll
        for (int nt = 0; nt < 8; nt++) {
            const int col = nt*8 + tig*2;
            const float2 nz = *(const float2*)(noise + (size_t)b*HW + y*WW + col);
            float v0 = acc[m][nt][0]*dA + nA*nz.x;
            float v1 = acc[m][nt][1]*dA + nA*nz.y;
            float v2 = acc[m][nt][2]*dB + nB*nz.x;
            float v3 = acc[m][nt][3]*dB + nB*nz.y;
            v0 = v0 > 0.f ? v0 : 0.2f*v0;
            v1 = v1 > 0.f ? v1 : 0.2f*v1;
            v2 = v2 > 0.f ? v2 : 0.2f*v2;
            v3 = v3 > 0.f ? v3 : 0.2f*v3;
            *(float2*)(outp + (size_t)(b*CC + ocA)*HW + y*WW + col) = make_float2(v0, v1);
            *(float2*)(outp + (size_t)(b*CC + ocB)*HW + y*WW + col) = make_float2(v2, v3);
        }
    }
}

// ---------------------------------------------------------------------------
extern "C" void kernel_launch(void* const* d_in, const int* in_sizes, int n_in,
                              void* d_out, int out_size) {
    const float* x   = (const float*)d_in[0];
    const float* w1  = (const float*)d_in[1];
    const float* w2  = (const float*)d_in[2];
    const float* n1  = (const float*)d_in[3];
    const float* n2  = (const float*)d_in[4];
    const float* s1w = (const float*)d_in[5];
    const float* s1b = (const float*)d_in[6];
    const float* c1w = (const float*)d_in[7];
    const float* nw1 = (const float*)d_in[8];
    const float* s2w = (const float*)d_in[9];
    const float* s2b = (const float*)d_in[10];
    const float* c2w = (const float*)d_in[11];
    const float* nw2 = (const float*)d_in[12];
    float* out = (float*)d_out;

    static int configured = 0;
    if (!configured) {
        cudaFuncSetAttribute(k_conv, cudaFuncAttributeMaxDynamicSharedMemorySize, SM_BYTES);
        configured = 1;
    }

    dim3 cgrid(32, 2, BB);       // 32 row-pairs x 2 oc halves x 16 batches
    dim3 dgrid(BB, 1, 2);

    k_prep <<<928, 256>>>(w1, s1w, s1b, c1w, w2, s2w, s2b, c2w);
    k_demod<<<dgrid, 256>>>();

    k_conv <<<cgrid, 128, SM_BYTES>>>(x, out, n1, nw1, 0);
    k_conv <<<cgrid, 128, SM_BYTES>>>(x, out, n2, nw2, 1);
}